// round 14
// baseline (speedup 1.0000x reference)
#include <cuda_runtime.h>
#include <math.h>

#define BATCH 16384

// ---------------- scratch (static device globals; no runtime allocation) ----------------
__device__ float d_cg[615];
__device__ float d_T0[(size_t)BATCH * 224];        //  14.7 MB  (l3=0, K=224, d3=1)
__device__ float d_T1[(size_t)BATCH * 3 * 384];    //  75.5 MB  (l3=1, K=384, d3=3)
__device__ float d_T2[(size_t)BATCH * 5 * 352];    // 115.3 MB  (l3=2, K=352, d3=5)

// ---------------- packed f32x2 helpers --------------------------------------------------
__device__ __forceinline__ double bcast2(float a) {
    double r; asm("mov.b64 %0, {%1, %1};" : "=d"(r) : "f"(a)); return r;
}
__device__ __forceinline__ void dfma2(double& c, double a, double b) {
    asm("fma.rn.f32x2 %0, %1, %2, %0;" : "+d"(c) : "d"(a), "d"(b));
}
__device__ __forceinline__ float2 unpack2(double d) {
    float2 f; asm("mov.b64 {%0, %1}, %2;" : "=f"(f.x), "=f"(f.y) : "d"(d)); return f;
}

// ---------------- CG coefficient init (exact port of reference math, fp64) --------------
struct cd { double re, im; };
__device__ __forceinline__ cd cmul(cd a, cd b) {
    return { a.re*b.re - a.im*b.im, a.re*b.im + a.im*b.re };
}

__device__ double dfact(int n) { double r = 1.0; for (int i = 2; i <= n; i++) r *= i; return r; }

__device__ double su2cg(int j1, int j2, int j3, int m1, int m2, int m3) {
    if (m3 != m1 + m2) return 0.0;
    double pref = sqrt((2.0*j3 + 1.0) * dfact(j1+j2-j3) * dfact(j1-j2+j3) * dfact(-j1+j2+j3)
                       / dfact(j1+j2+j3+1));
    pref *= sqrt(dfact(j3+m3)*dfact(j3-m3)*dfact(j1-m1)*dfact(j1+m1)*dfact(j2-m2)*dfact(j2+m2));
    double s = 0.0;
    for (int v = 0; v <= j1 + j2 - j3; v++) {
        int a = j1+j2-j3-v, b = j1-m1-v, c = j2+m2-v, d = j3-j2+m1+v, e = j3-j1-m2+v;
        if (a < 0 || b < 0 || c < 0 || d < 0 || e < 0) continue;
        double term = 1.0 / (dfact(v)*dfact(a)*dfact(b)*dfact(c)*dfact(d)*dfact(e));
        s += (v & 1) ? -term : term;
    }
    return pref * s;
}

// Q[r][c] for real->complex SH change of basis, including (-i)^l factor. r,c in [0,2l].
__device__ cd Qmat(int l, int r, int c) {
    int m = r - l;
    cd v = {0.0, 0.0};
    const double s = 0.7071067811865476;
    if (m < 0) {
        if (c == l - m)      v = { s, 0.0 };
        else if (c == l + m) v = { 0.0, -s };
    } else if (m == 0) {
        if (c == l) v = { 1.0, 0.0 };
    } else {
        double sg = (m & 1) ? -1.0 : 1.0;
        if (c == l + m)      v = { sg * s, 0.0 };
        else if (c == l - m) v = { 0.0, sg * s };
    }
    switch (l & 3) {                  // multiply by (-i)^l
        case 1: return { v.im, -v.re };
        case 2: return { -v.re, -v.im };
        default: return v;
    }
}

// 15 CG tensors, flattened. {l1,l2,l3,offset}; element (i1,i2,i3) at off+(i1*d2+i2)*d3+i3
__device__ const int d_keys[15][4] = {
    {0,0,0,  0},{0,1,1,  1},{0,2,2, 10},{1,0,1, 35},{1,1,0, 44},
    {1,1,1, 53},{1,1,2, 80},{1,2,1,125},{1,2,2,170},{2,0,2,245},
    {2,1,1,270},{2,1,2,315},{2,2,0,390},{2,2,1,415},{2,2,2,490}
};

// One block per coefficient; one (i,k) term per lane; warp-reduce in fp64.
__global__ void init_cg_kernel() {
    int t = blockIdx.x;                 // 0..614
    int key = 0;
    for (int kk = 14; kk >= 0; kk--) { if (t >= d_keys[kk][3]) { key = kk; break; } }
    int l1 = d_keys[key][0], l2 = d_keys[key][1], l3 = d_keys[key][2], off = d_keys[key][3];
    int d2 = 2*l2 + 1, d3 = 2*l3 + 1, d1 = 2*l1 + 1;
    int loc = t - off;
    int i1 = loc / (d2 * d3);
    int i2 = (loc / d3) % d2;
    int i3 = loc % d3;

    int tid = threadIdx.x;
    double re = 0.0;
    if (tid < d1 * d2) {
        int i = tid / d2, k = tid % d2;
        int n = (i - l1) + (k - l2) + l3;       // m3 = m1 + m2
        if (n >= 0 && n <= 2*l3) {
            double su = su2cg(l1, l2, l3, i - l1, k - l2, n - l3);
            if (su != 0.0) {
                cd q1 = Qmat(l1, i, i1);
                cd q2 = Qmat(l2, k, i2);
                cd q3 = Qmat(l3, n, i3); q3.im = -q3.im;   // conj
                cd p = cmul(cmul(q1, q2), q3);
                re = p.re * su;
            }
        }
    }
    #pragma unroll
    for (int o = 16; o > 0; o >>= 1) re += __shfl_down_sync(0xffffffffu, re, o);
    if (tid == 0) d_cg[t] = (float)re;
}

// ---------------- Phase 1: T_l3[b, k, u] = sum_i x[b,u,i] * g[b,i,k] --------------------
// Warp per batch; lanes parallel over multiplicity u -> coalesced stores. All 15 paths in
// one kernel so x is read once.
template<int L1, int L2, int L3, int MUL, int UOFF, int CGOFF, int K>
__device__ __forceinline__ void do_path(int b, int lane, const float* __restrict__ x,
                                        const float* yv, float* __restrict__ T) {
    constexpr int D1 = 2*L1 + 1, D2 = 2*L2 + 1, D3 = 2*L3 + 1;
    constexpr int XOFF = (L1 == 0) ? 0 : ((L1 == 1) ? 128 : 320);
    constexpr int YOFF = (L2 == 0) ? 0 : ((L2 == 1) ? 1 : 4);
    float g[D1][D3];
    #pragma unroll
    for (int i = 0; i < D1; i++)
        #pragma unroll
        for (int k = 0; k < D3; k++) {
            float a = 0.f;
            #pragma unroll
            for (int j = 0; j < D2; j++)
                a += d_cg[CGOFF + (i*D2 + j)*D3 + k] * yv[YOFF + j];
            g[i][k] = a;
        }
    const float* xb = x + (size_t)b * 480 + XOFF;
    float* Tb = T + (size_t)b * D3 * K + UOFF;
    #pragma unroll
    for (int c = 0; c < MUL / 32; c++) {
        int u = c * 32 + lane;
        float xv[D1];
        #pragma unroll
        for (int i = 0; i < D1; i++) xv[i] = xb[u*D1 + i];
        #pragma unroll
        for (int k = 0; k < D3; k++) {
            float a = 0.f;
            #pragma unroll
            for (int i = 0; i < D1; i++) a += xv[i] * g[i][k];
            Tb[k * K + u] = a;
        }
    }
}

__global__ void __launch_bounds__(256) build_T_kernel(const float* __restrict__ x,
                                                      const float* __restrict__ y) {
    int warp = threadIdx.x >> 5, lane = threadIdx.x & 31;
    int b = blockIdx.x * 8 + warp;
    float yv[9];
    #pragma unroll
    for (int j = 0; j < 9; j++) yv[j] = y[b*9 + j];
    // l3 = 0, K = 224
    do_path<0,0,0,128,  0,   0, 224>(b, lane, x, yv, d_T0);
    do_path<1,1,0, 64,128,  44, 224>(b, lane, x, yv, d_T0);
    do_path<2,2,0, 32,192, 390, 224>(b, lane, x, yv, d_T0);
    // l3 = 1, K = 384
    do_path<0,1,1,128,  0,   1, 384>(b, lane, x, yv, d_T1);
    do_path<1,0,1, 64,128,  35, 384>(b, lane, x, yv, d_T1);
    do_path<1,1,1, 64,192,  53, 384>(b, lane, x, yv, d_T1);
    do_path<1,2,1, 64,256, 125, 384>(b, lane, x, yv, d_T1);
    do_path<2,1,1, 32,320, 270, 384>(b, lane, x, yv, d_T1);
    do_path<2,2,1, 32,352, 415, 384>(b, lane, x, yv, d_T1);
    // l3 = 2, K = 352
    do_path<0,2,2,128,  0,  10, 352>(b, lane, x, yv, d_T2);
    do_path<1,1,2, 64,128,  80, 352>(b, lane, x, yv, d_T2);
    do_path<1,2,2, 64,192, 170, 352>(b, lane, x, yv, d_T2);
    do_path<2,0,2, 32,256, 245, 352>(b, lane, x, yv, d_T2);
    do_path<2,1,2, 32,288, 315, 352>(b, lane, x, yv, d_T2);
    do_path<2,2,2, 32,320, 490, 352>(b, lane, x, yv, d_T2);
}

// ---------------- Phase 2 (fused): out[b, SECT + v*D3 + k3] = scale*(T@W)[(b,k3), v] ----
// A tile transposed in smem (sA[kk][m], m contiguous -> packed a pairs via LDS.128, zero
// movs). W staged PRE-DUPLICATED as packed f32x2 doubles -> packed w via LDS.128, zero
// movs. fma.rn.f32x2 = 2 MACs/issue. One kernel hosts all three GEMMs (block-range
// dispatch) so the chip stays full across them.
constexpr int GEMM_SMEM_BYTES = 41472;   // max over the three variants

template<int WHICH, int KDIM, int N, int D3, int SECT, int TM, int TN>
__device__ __forceinline__ void gemm_body(int bid, char* smem_raw,
                                          const float* __restrict__ W,
                                          float* __restrict__ out, float scale) {
    constexpr int THREADS = 256;
    constexpr int TX = N / TN, TY = THREADS / TX, MT = TY * TM;
    static_assert(TX * TY == THREADS, "thread shape");
    static_assert(TM % 4 == 0 && TN % 2 == 0, "packing");
    constexpr int KT = 32, MTP = MT + 4;
    static_assert(KT * MTP * 4 + KT * N * 8 <= GEMM_SMEM_BYTES, "smem");
    float*  sA  = reinterpret_cast<float*>(smem_raw);                  // [KT][MTP]
    double* sWd = reinterpret_cast<double*>(smem_raw + KT * MTP * 4);  // [KT][N] duplicated

    const float* A = (WHICH == 0) ? d_T0 : (WHICH == 1) ? d_T1 : d_T2;

    int tid = threadIdx.x;
    int tx = tid % TX, ty = tid / TX;
    int bm0 = bid * MT;

    double acc[TM/2][TN];
    #pragma unroll
    for (int i = 0; i < TM/2; i++)
        #pragma unroll
        for (int j = 0; j < TN; j++) acc[i][j] = 0.0;   // bits == two 0.0f

    for (int k0 = 0; k0 < KDIM; k0 += KT) {
        #pragma unroll 4
        for (int e = tid; e < MT * KT; e += THREADS) {
            int m = e / KT, kk = e % KT;
            sA[kk * MTP + m] = A[(size_t)(bm0 + m) * KDIM + k0 + kk];
        }
        #pragma unroll 4
        for (int e = tid; e < KT * N; e += THREADS) {
            int kk = e / N, v = e % N;
            sWd[kk * N + v] = bcast2(W[(size_t)(k0 + kk) * N + v]);
        }
        __syncthreads();
        #pragma unroll 4
        for (int kk = 0; kk < KT; kk++) {
            double a[TM/2];
            const double2* ap = reinterpret_cast<const double2*>(&sA[kk * MTP + ty * TM]);
            #pragma unroll
            for (int p = 0; p < TM/4; p++) { double2 t = ap[p]; a[2*p] = t.x; a[2*p+1] = t.y; }
            double w[TN];
            const double2* wp = reinterpret_cast<const double2*>(&sWd[kk * N + tx * TN]);
            #pragma unroll
            for (int q = 0; q < TN/2; q++) { double2 t = wp[q]; w[2*q] = t.x; w[2*q+1] = t.y; }
            #pragma unroll
            for (int i = 0; i < TM/2; i++)
                #pragma unroll
                for (int j = 0; j < TN; j++) dfma2(acc[i][j], a[i], w[j]);
        }
        __syncthreads();
    }

    if (D3 == 1) {
        #pragma unroll
        for (int i = 0; i < TM/2; i++) {
            float lo[TN], hi[TN];
            #pragma unroll
            for (int j = 0; j < TN; j++) {
                float2 p = unpack2(acc[i][j]);
                lo[j] = p.x * scale; hi[j] = p.y * scale;
            }
            int b0 = bm0 + ty * TM + 2*i;
            float* o0 = out + (size_t)b0 * 480 + SECT + tx * TN;
            float* o1 = o0 + 480;
            #pragma unroll
            for (int j4 = 0; j4 < TN; j4 += 4) {
                *reinterpret_cast<float4*>(o0 + j4) = { lo[j4], lo[j4+1], lo[j4+2], lo[j4+3] };
                *reinterpret_cast<float4*>(o1 + j4) = { hi[j4], hi[j4+1], hi[j4+2], hi[j4+3] };
            }
        }
    } else {
        #pragma unroll
        for (int i = 0; i < TM/2; i++) {
            #pragma unroll
            for (int h = 0; h < 2; h++) {
                int m = bm0 + ty * TM + 2*i + h;
                int b = m / D3, k3 = m % D3;
                float* o = out + (size_t)b * 480 + SECT + k3;
                #pragma unroll
                for (int j = 0; j < TN; j++) {
                    float2 p = unpack2(acc[i][j]);
                    float v = (h == 0) ? p.x : p.y;
                    o[(tx * TN + j) * D3] = v * scale;
                }
            }
        }
    }
}

__global__ void __launch_bounds__(256)
fused_gemm_kernel(const float* __restrict__ W0, const float* __restrict__ W1,
                  const float* __restrict__ W2, float* __restrict__ out,
                  float s0, float s1, float s2) {
    __shared__ __align__(16) char smem_raw[GEMM_SMEM_BYTES];
    int bid = blockIdx.x;
    if (bid < 256) {
        // l3=0: M=16384, K=224, N=128, TM=4, TN=8 -> MT=64, 256 blocks
        gemm_body<0, 224, 128, 1,   0, 4, 8>(bid, smem_raw, W0, out, s0);
    } else if (bid < 640) {
        // l3=1: M=49152, K=384, N=64, TM=8, TN=4 -> MT=128, 384 blocks
        gemm_body<1, 384,  64, 3, 128, 8, 4>(bid - 256, smem_raw, W1, out, s1);
    } else {
        // l3=2: M=81920, K=352, N=32, TM=8, TN=4 -> MT=256, 320 blocks
        gemm_body<2, 352,  32, 5, 320, 8, 4>(bid - 640, smem_raw, W2, out, s2);
    }
}

// ---------------- launch ----------------
extern "C" void kernel_launch(void* const* d_in, const int* in_sizes, int n_in,
                              void* d_out, int out_size) {
    const float* x  = (const float*)d_in[0];
    const float* y  = (const float*)d_in[1];
    const float* W0 = (const float*)d_in[2];   // [224,128]
    const float* W1 = (const float*)d_in[3];   // [384,64]
    const float* W2 = (const float*)d_in[4];   // [352,32]
    float* out = (float*)d_out;

    init_cg_kernel<<<615, 32>>>();

    build_T_kernel<<<BATCH / 8, 256>>>(x, y);

    const float s0 = 1.0f / sqrtf(224.0f);
    const float s1 = 1.0f / sqrtf(384.0f);
    const float s2 = 1.0f / sqrtf(352.0f);

    fused_gemm_kernel<<<960, 256>>>(W0, W1, W2, out, s0, s1, s2);
}

// round 15
// speedup vs baseline: 1.3387x; 1.3387x over previous
#include <cuda_runtime.h>
#include <math.h>

#define BATCH 16384

// ---------------- scratch (static device globals; no runtime allocation) ----------------
__device__ float d_cg[615];
__device__ float d_T0[(size_t)BATCH * 224];        //  14.7 MB  (l3=0, K=224, d3=1)
__device__ float d_T1[(size_t)BATCH * 3 * 384];    //  75.5 MB  (l3=1, K=384, d3=3)
__device__ float d_T2[(size_t)BATCH * 5 * 352];    // 115.3 MB  (l3=2, K=352, d3=5)

// ---------------- packed f32x2 helpers --------------------------------------------------
__device__ __forceinline__ double bcast2(float a) {
    double r; asm("mov.b64 %0, {%1, %1};" : "=d"(r) : "f"(a)); return r;
}
__device__ __forceinline__ void dfma2(double& c, double a, double b) {
    asm("fma.rn.f32x2 %0, %1, %2, %0;" : "+d"(c) : "d"(a), "d"(b));
}
__device__ __forceinline__ float2 unpack2(double d) {
    float2 f; asm("mov.b64 {%0, %1}, %2;" : "=f"(f.x), "=f"(f.y) : "d"(d)); return f;
}

// ---------------- CG coefficient init (exact port of reference math, fp64) --------------
struct cd { double re, im; };
__device__ __forceinline__ cd cmul(cd a, cd b) {
    return { a.re*b.re - a.im*b.im, a.re*b.im + a.im*b.re };
}

__device__ double dfact(int n) { double r = 1.0; for (int i = 2; i <= n; i++) r *= i; return r; }

__device__ double su2cg(int j1, int j2, int j3, int m1, int m2, int m3) {
    if (m3 != m1 + m2) return 0.0;
    double pref = sqrt((2.0*j3 + 1.0) * dfact(j1+j2-j3) * dfact(j1-j2+j3) * dfact(-j1+j2+j3)
                       / dfact(j1+j2+j3+1));
    pref *= sqrt(dfact(j3+m3)*dfact(j3-m3)*dfact(j1-m1)*dfact(j1+m1)*dfact(j2-m2)*dfact(j2+m2));
    double s = 0.0;
    for (int v = 0; v <= j1 + j2 - j3; v++) {
        int a = j1+j2-j3-v, b = j1-m1-v, c = j2+m2-v, d = j3-j2+m1+v, e = j3-j1-m2+v;
        if (a < 0 || b < 0 || c < 0 || d < 0 || e < 0) continue;
        double term = 1.0 / (dfact(v)*dfact(a)*dfact(b)*dfact(c)*dfact(d)*dfact(e));
        s += (v & 1) ? -term : term;
    }
    return pref * s;
}

// Q[r][c] for real->complex SH change of basis, including (-i)^l factor. r,c in [0,2l].
__device__ cd Qmat(int l, int r, int c) {
    int m = r - l;
    cd v = {0.0, 0.0};
    const double s = 0.7071067811865476;
    if (m < 0) {
        if (c == l - m)      v = { s, 0.0 };
        else if (c == l + m) v = { 0.0, -s };
    } else if (m == 0) {
        if (c == l) v = { 1.0, 0.0 };
    } else {
        double sg = (m & 1) ? -1.0 : 1.0;
        if (c == l + m)      v = { sg * s, 0.0 };
        else if (c == l - m) v = { 0.0, sg * s };
    }
    switch (l & 3) {                  // multiply by (-i)^l
        case 1: return { v.im, -v.re };
        case 2: return { -v.re, -v.im };
        default: return v;
    }
}

// 15 CG tensors, flattened. {l1,l2,l3,offset}; element (i1,i2,i3) at off+(i1*d2+i2)*d3+i3
__device__ const int d_keys[15][4] = {
    {0,0,0,  0},{0,1,1,  1},{0,2,2, 10},{1,0,1, 35},{1,1,0, 44},
    {1,1,1, 53},{1,1,2, 80},{1,2,1,125},{1,2,2,170},{2,0,2,245},
    {2,1,1,270},{2,1,2,315},{2,2,0,390},{2,2,1,415},{2,2,2,490}
};

// One block per coefficient; one (i,k) term per lane; warp-reduce in fp64.
__global__ void init_cg_kernel() {
    int t = blockIdx.x;                 // 0..614
    int key = 0;
    for (int kk = 14; kk >= 0; kk--) { if (t >= d_keys[kk][3]) { key = kk; break; } }
    int l1 = d_keys[key][0], l2 = d_keys[key][1], l3 = d_keys[key][2], off = d_keys[key][3];
    int d2 = 2*l2 + 1, d3 = 2*l3 + 1, d1 = 2*l1 + 1;
    int loc = t - off;
    int i1 = loc / (d2 * d3);
    int i2 = (loc / d3) % d2;
    int i3 = loc % d3;

    int tid = threadIdx.x;
    double re = 0.0;
    if (tid < d1 * d2) {
        int i = tid / d2, k = tid % d2;
        int n = (i - l1) + (k - l2) + l3;       // m3 = m1 + m2
        if (n >= 0 && n <= 2*l3) {
            double su = su2cg(l1, l2, l3, i - l1, k - l2, n - l3);
            if (su != 0.0) {
                cd q1 = Qmat(l1, i, i1);
                cd q2 = Qmat(l2, k, i2);
                cd q3 = Qmat(l3, n, i3); q3.im = -q3.im;   // conj
                cd p = cmul(cmul(q1, q2), q3);
                re = p.re * su;
            }
        }
    }
    #pragma unroll
    for (int o = 16; o > 0; o >>= 1) re += __shfl_down_sync(0xffffffffu, re, o);
    if (tid == 0) d_cg[t] = (float)re;
}

// ---------------- Phase 1: T_l3[b, k, u] = sum_i x[b,u,i] * g[b,i,k] --------------------
// Warp per batch; lanes parallel over multiplicity u -> coalesced stores.
template<int L1, int L2, int L3, int MUL, int UOFF, int CGOFF, int K>
__device__ __forceinline__ void do_path(int b, int lane, const float* __restrict__ x,
                                        const float* yv, float* __restrict__ T) {
    constexpr int D1 = 2*L1 + 1, D2 = 2*L2 + 1, D3 = 2*L3 + 1;
    constexpr int XOFF = (L1 == 0) ? 0 : ((L1 == 1) ? 128 : 320);
    constexpr int YOFF = (L2 == 0) ? 0 : ((L2 == 1) ? 1 : 4);
    float g[D1][D3];
    #pragma unroll
    for (int i = 0; i < D1; i++)
        #pragma unroll
        for (int k = 0; k < D3; k++) {
            float a = 0.f;
            #pragma unroll
            for (int j = 0; j < D2; j++)
                a += d_cg[CGOFF + (i*D2 + j)*D3 + k] * yv[YOFF + j];
            g[i][k] = a;
        }
    const float* xb = x + (size_t)b * 480 + XOFF;
    float* Tb = T + (size_t)b * D3 * K + UOFF;
    #pragma unroll
    for (int c = 0; c < MUL / 32; c++) {
        int u = c * 32 + lane;
        float xv[D1];
        #pragma unroll
        for (int i = 0; i < D1; i++) xv[i] = xb[u*D1 + i];
        #pragma unroll
        for (int k = 0; k < D3; k++) {
            float a = 0.f;
            #pragma unroll
            for (int i = 0; i < D1; i++) a += xv[i] * g[i][k];
            Tb[k * K + u] = a;
        }
    }
}

__global__ void build_T_kernel(const float* __restrict__ x, const float* __restrict__ y) {
    int warp = threadIdx.x >> 5, lane = threadIdx.x & 31;
    int b = blockIdx.x * (blockDim.x >> 5) + warp;
    if (b >= BATCH) return;
    float yv[9];
    #pragma unroll
    for (int j = 0; j < 9; j++) yv[j] = y[b*9 + j];
    int grp = blockIdx.y;
    if (grp == 0) {            // l3 = 0, K = 224
        do_path<0,0,0,128,  0,   0, 224>(b, lane, x, yv, d_T0);
        do_path<1,1,0, 64,128,  44, 224>(b, lane, x, yv, d_T0);
        do_path<2,2,0, 32,192, 390, 224>(b, lane, x, yv, d_T0);
    } else if (grp == 1) {     // l3 = 1, K = 384
        do_path<0,1,1,128,  0,   1, 384>(b, lane, x, yv, d_T1);
        do_path<1,0,1, 64,128,  35, 384>(b, lane, x, yv, d_T1);
        do_path<1,1,1, 64,192,  53, 384>(b, lane, x, yv, d_T1);
        do_path<1,2,1, 64,256, 125, 384>(b, lane, x, yv, d_T1);
        do_path<2,1,1, 32,320, 270, 384>(b, lane, x, yv, d_T1);
        do_path<2,2,1, 32,352, 415, 384>(b, lane, x, yv, d_T1);
    } else {                   // l3 = 2, K = 352
        do_path<0,2,2,128,  0,  10, 352>(b, lane, x, yv, d_T2);
        do_path<1,1,2, 64,128,  80, 352>(b, lane, x, yv, d_T2);
        do_path<1,2,2, 64,192, 170, 352>(b, lane, x, yv, d_T2);
        do_path<2,0,2, 32,256, 245, 352>(b, lane, x, yv, d_T2);
        do_path<2,1,2, 32,288, 315, 352>(b, lane, x, yv, d_T2);
        do_path<2,2,2, 32,320, 490, 352>(b, lane, x, yv, d_T2);
    }
}

// ---------------- Phase 2: out[b, SECT + v*D3 + k] = scale * (T @ W)[(b,k), v] ----------
// A tile transposed in smem (sA[kk][m], m contiguous). Accumulators are PACKED OVER M:
// a packed-pair of adjacent m-values comes straight from LDS.128 (no movs); only the TN
// w-values need a bcast mov each. fma.rn.f32x2 does 2 MACs per issue.
// TM=4, TN=4 everywhere: 16 outputs/thread so the grids are large enough to put ~40
// warps on every SM (R13's 32-outputs/thread grids starved the SMs at ~21 warps/SM).
template<int WHICH, int KDIM, int N, int D3, int SECT, int THREADS, int TM, int TN>
__global__ void __launch_bounds__(THREADS)
gemm_T_kernel(const float* __restrict__ W, float* __restrict__ out, float scale) {
    constexpr int TX = N / TN, TY = THREADS / TX, MT = TY * TM;
    static_assert(TX * TY == THREADS, "thread shape");
    static_assert(TM % 4 == 0, "TM multiple of 4 for packed LDS.128");
    constexpr int KT = 32, MTP = MT + 4;
    __shared__ __align__(16) float sA[KT * MTP];   // transposed A tile
    __shared__ __align__(16) float sW[KT * N];

    const float* A = (WHICH == 0) ? d_T0 : (WHICH == 1) ? d_T1 : d_T2;

    int tid = threadIdx.x;
    int tx = tid % TX, ty = tid / TX;
    int bm0 = blockIdx.x * MT;

    double acc[TM/2][TN];
    #pragma unroll
    for (int i = 0; i < TM/2; i++)
        #pragma unroll
        for (int j = 0; j < TN; j++) acc[i][j] = 0.0;   // bits == two 0.0f

    for (int k0 = 0; k0 < KDIM; k0 += KT) {
        // A: global coalesced along k (lane = kk), transposed store into sA[kk][m]
        #pragma unroll 4
        for (int e = tid; e < MT * KT; e += THREADS) {
            int m = e / KT, kk = e % KT;
            sA[kk * MTP + m] = A[(size_t)(bm0 + m) * KDIM + k0 + kk];
        }
        #pragma unroll 4
        for (int e = tid; e < KT * N; e += THREADS) {
            int kk = e / N, v = e % N;
            sW[kk * N + v] = W[(size_t)(k0 + kk) * N + v];
        }
        __syncthreads();
        #pragma unroll 4
        for (int kk = 0; kk < KT; kk++) {
            // packed a: TM/2 f32x2 pairs straight from smem (broadcast across tx lanes)
            double a[TM/2];
            const double2* ap = reinterpret_cast<const double2*>(&sA[kk * MTP + ty * TM]);
            #pragma unroll
            for (int p = 0; p < TM/4; p++) { double2 t = ap[p]; a[2*p] = t.x; a[2*p+1] = t.y; }
            // w: TN scalars -> broadcast-packed
            float wf[TN];
            #pragma unroll
            for (int j4 = 0; j4 < TN; j4 += 4) {
                float4 wv = *reinterpret_cast<const float4*>(&sW[kk * N + tx * TN + j4]);
                wf[j4+0] = wv.x; wf[j4+1] = wv.y; wf[j4+2] = wv.z; wf[j4+3] = wv.w;
            }
            double wp[TN];
            #pragma unroll
            for (int j = 0; j < TN; j++) wp[j] = bcast2(wf[j]);
            #pragma unroll
            for (int i = 0; i < TM/2; i++)
                #pragma unroll
                for (int j = 0; j < TN; j++) dfma2(acc[i][j], a[i], wp[j]);
        }
        __syncthreads();
    }

    if (D3 == 1) {
        // rows are whole batches; unpack m-pairs, contiguous float4 stores
        #pragma unroll
        for (int i = 0; i < TM/2; i++) {
            float lo[TN], hi[TN];
            #pragma unroll
            for (int j = 0; j < TN; j++) {
                float2 p = unpack2(acc[i][j]);
                lo[j] = p.x * scale; hi[j] = p.y * scale;
            }
            int b0 = bm0 + ty * TM + 2*i;
            float* o0 = out + (size_t)b0 * 480 + SECT + tx * TN;
            float* o1 = o0 + 480;
            #pragma unroll
            for (int j4 = 0; j4 < TN; j4 += 4) {
                *reinterpret_cast<float4*>(o0 + j4) = { lo[j4], lo[j4+1], lo[j4+2], lo[j4+3] };
                *reinterpret_cast<float4*>(o1 + j4) = { hi[j4], hi[j4+1], hi[j4+2], hi[j4+3] };
            }
        }
    } else {
        // scattered stores: out[b*480 + SECT + v*D3 + k3]
        #pragma unroll
        for (int i = 0; i < TM/2; i++) {
            #pragma unroll
            for (int h = 0; h < 2; h++) {
                int m = bm0 + ty * TM + 2*i + h;
                int b = m / D3, k3 = m % D3;
                float* o = out + (size_t)b * 480 + SECT + k3;
                #pragma unroll
                for (int j = 0; j < TN; j++) {
                    float2 p = unpack2(acc[i][j]);
                    float v = (h == 0) ? p.x : p.y;
                    o[(tx * TN + j) * D3] = v * scale;
                }
            }
        }
    }
}

// ---------------- launch ----------------
extern "C" void kernel_launch(void* const* d_in, const int* in_sizes, int n_in,
                              void* d_out, int out_size) {
    const float* x  = (const float*)d_in[0];
    const float* y  = (const float*)d_in[1];
    const float* W0 = (const float*)d_in[2];   // [224,128]
    const float* W1 = (const float*)d_in[3];   // [384,64]
    const float* W2 = (const float*)d_in[4];   // [352,32]
    float* out = (float*)d_out;

    init_cg_kernel<<<615, 32>>>();

    dim3 g1(BATCH / 8, 3);                     // warp per batch, 8 warps/block
    build_T_kernel<<<g1, 256>>>(x, y);

    const float s0 = 1.0f / sqrtf(224.0f);
    const float s1 = 1.0f / sqrtf(384.0f);
    const float s2 = 1.0f / sqrtf(352.0f);

    // l3=0: M=16384, K=224, N=128: 256 thr, TM=4, TN=4 -> MT=32,  512 blocks
    gemm_T_kernel<0, 224, 128, 1,   0, 256, 4, 4><<<BATCH * 1 /  32, 256>>>(W0, out, s0);
    // l3=1: M=49152, K=384, N=64:  256 thr, TM=4, TN=4 -> MT=64,  768 blocks
    gemm_T_kernel<1, 384,  64, 3, 128, 256, 4, 4><<<BATCH * 3 /  64, 256>>>(W1, out, s1);
    // l3=2: M=81920, K=352, N=32:  256 thr, TM=4, TN=4 -> MT=128, 640 blocks
    gemm_T_kernel<2, 352,  32, 5, 320, 256, 4, 4><<<BATCH * 5 / 128, 256>>>(W2, out, s2);
}

// round 16
// speedup vs baseline: 1.5597x; 1.1651x over previous
#include <cuda_runtime.h>
#include <math.h>

#define BATCH 16384

// ---------------- scratch (static device globals; no runtime allocation) ----------------
__device__ float d_cg[615];
__device__ float d_T0[(size_t)BATCH * 224];        //  14.7 MB  (l3=0, K=224, d3=1)
__device__ float d_T1[(size_t)BATCH * 3 * 384];    //  75.5 MB  (l3=1, K=384, d3=3)
__device__ float d_T2[(size_t)BATCH * 5 * 352];    // 115.3 MB  (l3=2, K=352, d3=5)

// ---------------- packed f32x2 helpers --------------------------------------------------
__device__ __forceinline__ double bcast2(float a) {
    double r; asm("mov.b64 %0, {%1, %1};" : "=d"(r) : "f"(a)); return r;
}
__device__ __forceinline__ void dfma2(double& c, double a, double b) {
    asm("fma.rn.f32x2 %0, %1, %2, %0;" : "+d"(c) : "d"(a), "d"(b));
}
__device__ __forceinline__ float2 unpack2(double d) {
    float2 f; asm("mov.b64 {%0, %1}, %2;" : "=f"(f.x), "=f"(f.y) : "d"(d)); return f;
}

// ---------------- CG coefficient init (exact port of reference math, fp64) --------------
struct cd { double re, im; };
__device__ __forceinline__ cd cmul(cd a, cd b) {
    return { a.re*b.re - a.im*b.im, a.re*b.im + a.im*b.re };
}

__device__ double dfact(int n) { double r = 1.0; for (int i = 2; i <= n; i++) r *= i; return r; }

__device__ double su2cg(int j1, int j2, int j3, int m1, int m2, int m3) {
    if (m3 != m1 + m2) return 0.0;
    double pref = sqrt((2.0*j3 + 1.0) * dfact(j1+j2-j3) * dfact(j1-j2+j3) * dfact(-j1+j2+j3)
                       / dfact(j1+j2+j3+1));
    pref *= sqrt(dfact(j3+m3)*dfact(j3-m3)*dfact(j1-m1)*dfact(j1+m1)*dfact(j2-m2)*dfact(j2+m2));
    double s = 0.0;
    for (int v = 0; v <= j1 + j2 - j3; v++) {
        int a = j1+j2-j3-v, b = j1-m1-v, c = j2+m2-v, d = j3-j2+m1+v, e = j3-j1-m2+v;
        if (a < 0 || b < 0 || c < 0 || d < 0 || e < 0) continue;
        double term = 1.0 / (dfact(v)*dfact(a)*dfact(b)*dfact(c)*dfact(d)*dfact(e));
        s += (v & 1) ? -term : term;
    }
    return pref * s;
}

// Q[r][c] for real->complex SH change of basis, including (-i)^l factor. r,c in [0,2l].
__device__ cd Qmat(int l, int r, int c) {
    int m = r - l;
    cd v = {0.0, 0.0};
    const double s = 0.7071067811865476;
    if (m < 0) {
        if (c == l - m)      v = { s, 0.0 };
        else if (c == l + m) v = { 0.0, -s };
    } else if (m == 0) {
        if (c == l) v = { 1.0, 0.0 };
    } else {
        double sg = (m & 1) ? -1.0 : 1.0;
        if (c == l + m)      v = { sg * s, 0.0 };
        else if (c == l - m) v = { 0.0, sg * s };
    }
    switch (l & 3) {                  // multiply by (-i)^l
        case 1: return { v.im, -v.re };
        case 2: return { -v.re, -v.im };
        default: return v;
    }
}

// 15 CG tensors, flattened. {l1,l2,l3,offset}; element (i1,i2,i3) at off+(i1*d2+i2)*d3+i3
__device__ const int d_keys[15][4] = {
    {0,0,0,  0},{0,1,1,  1},{0,2,2, 10},{1,0,1, 35},{1,1,0, 44},
    {1,1,1, 53},{1,1,2, 80},{1,2,1,125},{1,2,2,170},{2,0,2,245},
    {2,1,1,270},{2,1,2,315},{2,2,0,390},{2,2,1,415},{2,2,2,490}
};

// One block per coefficient; one (i,k) term per lane; warp-reduce in fp64.
__global__ void init_cg_kernel() {
    int t = blockIdx.x;                 // 0..614
    int key = 0;
    for (int kk = 14; kk >= 0; kk--) { if (t >= d_keys[kk][3]) { key = kk; break; } }
    int l1 = d_keys[key][0], l2 = d_keys[key][1], l3 = d_keys[key][2], off = d_keys[key][3];
    int d2 = 2*l2 + 1, d3 = 2*l3 + 1, d1 = 2*l1 + 1;
    int loc = t - off;
    int i1 = loc / (d2 * d3);
    int i2 = (loc / d3) % d2;
    int i3 = loc % d3;

    int tid = threadIdx.x;
    double re = 0.0;
    if (tid < d1 * d2) {
        int i = tid / d2, k = tid % d2;
        int n = (i - l1) + (k - l2) + l3;       // m3 = m1 + m2
        if (n >= 0 && n <= 2*l3) {
            double su = su2cg(l1, l2, l3, i - l1, k - l2, n - l3);
            if (su != 0.0) {
                cd q1 = Qmat(l1, i, i1);
                cd q2 = Qmat(l2, k, i2);
                cd q3 = Qmat(l3, n, i3); q3.im = -q3.im;   // conj
                cd p = cmul(cmul(q1, q2), q3);
                re = p.re * su;
            }
        }
    }
    #pragma unroll
    for (int o = 16; o > 0; o >>= 1) re += __shfl_down_sync(0xffffffffu, re, o);
    if (tid == 0) d_cg[t] = (float)re;
}

// ---------------- Phase 1: T_l3[b, k, u] = sum_i x[b,u,i] * g[b,i,k] --------------------
// Warp per batch; lanes parallel over multiplicity u -> coalesced stores.
template<int L1, int L2, int L3, int MUL, int UOFF, int CGOFF, int K>
__device__ __forceinline__ void do_path(int b, int lane, const float* __restrict__ x,
                                        const float* yv, float* __restrict__ T) {
    constexpr int D1 = 2*L1 + 1, D2 = 2*L2 + 1, D3 = 2*L3 + 1;
    constexpr int XOFF = (L1 == 0) ? 0 : ((L1 == 1) ? 128 : 320);
    constexpr int YOFF = (L2 == 0) ? 0 : ((L2 == 1) ? 1 : 4);
    float g[D1][D3];
    #pragma unroll
    for (int i = 0; i < D1; i++)
        #pragma unroll
        for (int k = 0; k < D3; k++) {
            float a = 0.f;
            #pragma unroll
            for (int j = 0; j < D2; j++)
                a += d_cg[CGOFF + (i*D2 + j)*D3 + k] * yv[YOFF + j];
            g[i][k] = a;
        }
    const float* xb = x + (size_t)b * 480 + XOFF;
    float* Tb = T + (size_t)b * D3 * K + UOFF;
    #pragma unroll
    for (int c = 0; c < MUL / 32; c++) {
        int u = c * 32 + lane;
        float xv[D1];
        #pragma unroll
        for (int i = 0; i < D1; i++) xv[i] = xb[u*D1 + i];
        #pragma unroll
        for (int k = 0; k < D3; k++) {
            float a = 0.f;
            #pragma unroll
            for (int i = 0; i < D1; i++) a += xv[i] * g[i][k];
            Tb[k * K + u] = a;
        }
    }
}

__global__ void build_T_kernel(const float* __restrict__ x, const float* __restrict__ y) {
    int warp = threadIdx.x >> 5, lane = threadIdx.x & 31;
    int b = blockIdx.x * (blockDim.x >> 5) + warp;
    if (b >= BATCH) return;
    float yv[9];
    #pragma unroll
    for (int j = 0; j < 9; j++) yv[j] = y[b*9 + j];
    int grp = blockIdx.y;
    if (grp == 0) {            // l3 = 0, K = 224
        do_path<0,0,0,128,  0,   0, 224>(b, lane, x, yv, d_T0);
        do_path<1,1,0, 64,128,  44, 224>(b, lane, x, yv, d_T0);
        do_path<2,2,0, 32,192, 390, 224>(b, lane, x, yv, d_T0);
    } else if (grp == 1) {     // l3 = 1, K = 384
        do_path<0,1,1,128,  0,   1, 384>(b, lane, x, yv, d_T1);
        do_path<1,0,1, 64,128,  35, 384>(b, lane, x, yv, d_T1);
        do_path<1,1,1, 64,192,  53, 384>(b, lane, x, yv, d_T1);
        do_path<1,2,1, 64,256, 125, 384>(b, lane, x, yv, d_T1);
        do_path<2,1,1, 32,320, 270, 384>(b, lane, x, yv, d_T1);
        do_path<2,2,1, 32,352, 415, 384>(b, lane, x, yv, d_T1);
    } else {                   // l3 = 2, K = 352
        do_path<0,2,2,128,  0,  10, 352>(b, lane, x, yv, d_T2);
        do_path<1,1,2, 64,128,  80, 352>(b, lane, x, yv, d_T2);
        do_path<1,2,2, 64,192, 170, 352>(b, lane, x, yv, d_T2);
        do_path<2,0,2, 32,256, 245, 352>(b, lane, x, yv, d_T2);
        do_path<2,1,2, 32,288, 315, 352>(b, lane, x, yv, d_T2);
        do_path<2,2,2, 32,320, 490, 352>(b, lane, x, yv, d_T2);
    }
}

// ---------------- Phase 2 (fused dispatch): one launch hosts all three GEMMs ------------
// Body identical to the proven R13/R15 gemm_T_kernel: A tile transposed in smem
// (sA[kk][m], m contiguous -> packed f32x2 'a' pairs straight from LDS.128), W broadcast-
// packed per kk, fma.rn.f32x2 = 2 MACs/issue. Fill across segments comes from
// co-residency, so each segment uses its per-block-efficiency-optimal tile.
constexpr int GEMM_SMEM_BYTES = 25088;   // max over the three variants below

template<int WHICH, int KDIM, int N, int D3, int SECT, int TM, int TN>
__device__ __forceinline__ void gemm_body(int bid, char* smem_raw,
                                          const float* __restrict__ W,
                                          float* __restrict__ out, float scale) {
    constexpr int THREADS = 256;
    constexpr int TX = N / TN, TY = THREADS / TX, MT = TY * TM;
    static_assert(TX * TY == THREADS, "thread shape");
    static_assert(TM % 4 == 0, "TM multiple of 4 for packed LDS.128");
    constexpr int KT = 32, MTP = MT + 4;
    static_assert(KT * MTP * 4 + KT * N * 4 <= GEMM_SMEM_BYTES, "smem");
    float* sA = reinterpret_cast<float*>(smem_raw);              // [KT][MTP] transposed
    float* sW = reinterpret_cast<float*>(smem_raw) + KT * MTP;   // [KT][N]

    const float* A = (WHICH == 0) ? d_T0 : (WHICH == 1) ? d_T1 : d_T2;

    int tid = threadIdx.x;
    int tx = tid % TX, ty = tid / TX;
    int bm0 = bid * MT;

    double acc[TM/2][TN];
    #pragma unroll
    for (int i = 0; i < TM/2; i++)
        #pragma unroll
        for (int j = 0; j < TN; j++) acc[i][j] = 0.0;   // bits == two 0.0f

    for (int k0 = 0; k0 < KDIM; k0 += KT) {
        #pragma unroll 4
        for (int e = tid; e < MT * KT; e += THREADS) {
            int m = e / KT, kk = e % KT;
            sA[kk * MTP + m] = A[(size_t)(bm0 + m) * KDIM + k0 + kk];
        }
        #pragma unroll 4
        for (int e = tid; e < KT * N; e += THREADS) {
            int kk = e / N, v = e % N;
            sW[kk * N + v] = W[(size_t)(k0 + kk) * N + v];
        }
        __syncthreads();
        #pragma unroll 4
        for (int kk = 0; kk < KT; kk++) {
            double a[TM/2];
            const double2* ap = reinterpret_cast<const double2*>(&sA[kk * MTP + ty * TM]);
            #pragma unroll
            for (int p = 0; p < TM/4; p++) { double2 t = ap[p]; a[2*p] = t.x; a[2*p+1] = t.y; }
            float wf[TN];
            #pragma unroll
            for (int j4 = 0; j4 < TN; j4 += 4) {
                float4 wv = *reinterpret_cast<const float4*>(&sW[kk * N + tx * TN + j4]);
                wf[j4+0] = wv.x; wf[j4+1] = wv.y; wf[j4+2] = wv.z; wf[j4+3] = wv.w;
            }
            double wp[TN];
            #pragma unroll
            for (int j = 0; j < TN; j++) wp[j] = bcast2(wf[j]);
            #pragma unroll
            for (int i = 0; i < TM/2; i++)
                #pragma unroll
                for (int j = 0; j < TN; j++) dfma2(acc[i][j], a[i], wp[j]);
        }
        __syncthreads();
    }

    if (D3 == 1) {
        #pragma unroll
        for (int i = 0; i < TM/2; i++) {
            float lo[TN], hi[TN];
            #pragma unroll
            for (int j = 0; j < TN; j++) {
                float2 p = unpack2(acc[i][j]);
                lo[j] = p.x * scale; hi[j] = p.y * scale;
            }
            int b0 = bm0 + ty * TM + 2*i;
            float* o0 = out + (size_t)b0 * 480 + SECT + tx * TN;
            float* o1 = o0 + 480;
            #pragma unroll
            for (int j4 = 0; j4 < TN; j4 += 4) {
                *reinterpret_cast<float4*>(o0 + j4) = { lo[j4], lo[j4+1], lo[j4+2], lo[j4+3] };
                *reinterpret_cast<float4*>(o1 + j4) = { hi[j4], hi[j4+1], hi[j4+2], hi[j4+3] };
            }
        }
    } else {
        #pragma unroll
        for (int i = 0; i < TM/2; i++) {
            #pragma unroll
            for (int h = 0; h < 2; h++) {
                int m = bm0 + ty * TM + 2*i + h;
                int b = m / D3, k3 = m % D3;
                float* o = out + (size_t)b * 480 + SECT + k3;
                #pragma unroll
                for (int j = 0; j < TN; j++) {
                    float2 p = unpack2(acc[i][j]);
                    float v = (h == 0) ? p.x : p.y;
                    o[(tx * TN + j) * D3] = v * scale;
                }
            }
        }
    }
}

__global__ void __launch_bounds__(256)
fused_gemm_kernel(const float* __restrict__ W0, const float* __restrict__ W1,
                  const float* __restrict__ W2, float* __restrict__ out,
                  float s0, float s1, float s2) {
    __shared__ __align__(16) char smem_raw[GEMM_SMEM_BYTES];
    int bid = blockIdx.x;
    if (bid < 256) {
        // l3=0: M=16384, K=224, N=128, TM=4, TN=8 -> MT=64,  256 blocks (25.1 KB smem)
        gemm_body<0, 224, 128, 1,   0, 4, 8>(bid, smem_raw, W0, out, s0);
    } else if (bid < 640) {
        // l3=1: M=49152, K=384, N=64,  TM=8, TN=4 -> MT=128, 384 blocks (25.1 KB smem)
        gemm_body<1, 384,  64, 3, 128, 8, 4>(bid - 256, smem_raw, W1, out, s1);
    } else {
        // l3=2: M=81920, K=352, N=32,  TM=4, TN=4 -> MT=128, 640 blocks (21.0 KB smem)
        gemm_body<2, 352,  32, 5, 320, 4, 4>(bid - 640, smem_raw, W2, out, s2);
    }
}

// ---------------- launch ----------------
extern "C" void kernel_launch(void* const* d_in, const int* in_sizes, int n_in,
                              void* d_out, int out_size) {
    const float* x  = (const float*)d_in[0];
    const float* y  = (const float*)d_in[1];
    const float* W0 = (const float*)d_in[2];   // [224,128]
    const float* W1 = (const float*)d_in[3];   // [384,64]
    const float* W2 = (const float*)d_in[4];   // [352,32]
    float* out = (float*)d_out;

    init_cg_kernel<<<615, 32>>>();

    dim3 g1(BATCH / 8, 3);                     // warp per batch, 8 warps/block
    build_T_kernel<<<g1, 256>>>(x, y);

    const float s0 = 1.0f / sqrtf(224.0f);
    const float s1 = 1.0f / sqrtf(384.0f);
    const float s2 = 1.0f / sqrtf(352.0f);

    fused_gemm_kernel<<<1280, 256>>>(W0, W1, W2, out, s0, s1, s2);
}